// round 1
// baseline (speedup 1.0000x reference)
#include <cuda_runtime.h>
#include <cuda_bf16.h>
#include <math.h>

// Problem constants (match reference)
#define BG   64                 // graphs
#define NPG  2048               // nodes per graph
#define EPG  32768              // edges per graph
#define NTOT (BG * NPG)         // 131072 nodes total
#define EDG  (BG * EPG)         // 2097152 edges total
#define K1   1639
#define NT1  (BG * K1)          // 104896
#define K2   1312
#define NT2  (BG * K2)          // 83968
#define DIM  64
#define NCLS 6

// ---------------- scratch (allocation-free: __device__ globals) -------------
__device__ float g_xw[NTOT * DIM];    // x@W (stage1), xp@W2 (stage2)
__device__ float g_agg[NTOT * DIM];   // neighbor aggregation
__device__ float g_h[NTOT * DIM];     // conv output (relu'd)
__device__ float g_xp[(size_t)NT1 * DIM]; // pooled gated features (stage1 then stage2)
__device__ float g_deg[NTOT];
__device__ float g_score[NTOT];
__device__ int   g_perm[NT1];
__device__ float g_vals[NT1];
__device__ int   g_newid[NTOT];
__device__ int2  g_e2[EDG];
__device__ float g_x1[BG * 2 * DIM];
__device__ float g_x2[BG * 2 * DIM];

// ---------------- small utility kernels -------------------------------------
__global__ void fill_f_kernel(float* p, float v, long long n) {
    long long t = (long long)blockIdx.x * blockDim.x + threadIdx.x;
    long long stride = (long long)gridDim.x * blockDim.x;
    for (; t < n; t += stride) p[t] = v;
}
__global__ void fill_i_kernel(int* p, int v, long long n) {
    long long t = (long long)blockIdx.x * blockDim.x + threadIdx.x;
    long long stride = (long long)gridDim.x * blockDim.x;
    for (; t < n; t += stride) p[t] = v;
}

// deg[dst] += 1 for every edge (stage 1: all edges valid)
__global__ void deg1_kernel(const int* __restrict__ dst, float* __restrict__ deg, int nedges) {
    int t = blockIdx.x * blockDim.x + threadIdx.x;
    if (t < nedges) atomicAdd(&deg[dst[t]], 1.0f);
}

// map edges through newid; cache remapped endpoints; accumulate deg2
__global__ void edge_map_kernel(const int* __restrict__ src, const int* __restrict__ dst,
                                const int* __restrict__ newid, int2* __restrict__ e2,
                                float* __restrict__ deg2, int nedges) {
    int t = blockIdx.x * blockDim.x + threadIdx.x;
    if (t >= nedges) return;
    int s2 = newid[src[t]];
    int d2 = newid[dst[t]];
    if (s2 < 0 || d2 < 0) {
        e2[t] = make_int2(-1, -1);
    } else {
        e2[t] = make_int2(s2, d2);
        atomicAdd(&deg2[d2], 1.0f);
    }
}

// ---------------- GEMM: C[n x 64] = A[n x 64] @ W[64 x 64] ------------------
__global__ __launch_bounds__(256) void matmul64_kernel(
    const float* __restrict__ A, const float* __restrict__ W,
    float* __restrict__ C, int nrows) {
    __shared__ float Wt[64][68];   // Wt[j][k] = W[k][j], padded row (68 floats) for bank-free LDS128
    __shared__ float As[32][64];
    int tid = threadIdx.x;
    for (int i = tid; i < 64 * 64; i += 256) {
        int k = i >> 6, j = i & 63;
        Wt[j][k] = W[i];
    }
    int row0 = blockIdx.x * 32;
    {
        const float4* a4 = (const float4*)(A + (size_t)row0 * 64);
        float4* s4 = (float4*)&As[0][0];
        for (int i = tid; i < 512; i += 256) {
            int grow = row0 + (i >> 4);
            s4[i] = (grow < nrows) ? a4[i] : make_float4(0.f, 0.f, 0.f, 0.f);
        }
    }
    __syncthreads();
    int j  = tid & 31;    // columns j and j+32
    int rg = tid >> 5;    // row group 0..7 -> rows rg*4 .. rg*4+3
    float acc[4][2] = {};
#pragma unroll
    for (int k4 = 0; k4 < 16; k4++) {
        float4 w0 = *(const float4*)&Wt[j][k4 * 4];
        float4 w1 = *(const float4*)&Wt[j + 32][k4 * 4];
#pragma unroll
        for (int r = 0; r < 4; r++) {
            float4 a = *(const float4*)&As[rg * 4 + r][k4 * 4];
            acc[r][0] += a.x * w0.x + a.y * w0.y + a.z * w0.z + a.w * w0.w;
            acc[r][1] += a.x * w1.x + a.y * w1.y + a.z * w1.z + a.w * w1.w;
        }
    }
#pragma unroll
    for (int r = 0; r < 4; r++) {
        int row = row0 + rg * 4 + r;
        if (row < nrows) {
            C[(size_t)row * 64 + j]      = acc[r][0];
            C[(size_t)row * 64 + j + 32] = acc[r][1];
        }
    }
}

// ---------------- edge scatter (vectorized red.global.add.v4.f32) -----------
__device__ __forceinline__ void red_add_v4(float4* ptr, float a, float b, float c, float d) {
    asm volatile("red.global.add.v4.f32 [%0], {%1, %2, %3, %4};"
                 :: "l"(ptr), "f"(a), "f"(b), "f"(c), "f"(d) : "memory");
}

__global__ __launch_bounds__(256) void scatter1_kernel(
    const int* __restrict__ src, const int* __restrict__ dst,
    const float* __restrict__ deg, const float* __restrict__ xw,
    float* __restrict__ agg, int nedges) {
    long long t = (long long)blockIdx.x * blockDim.x + threadIdx.x;
    int e = (int)(t >> 4);
    int c = (int)(t & 15);
    if (e >= nedges) return;
    int s = src[e], d = dst[e];
    float norm = rsqrtf(deg[s] * deg[d]);
    float4 v = ((const float4*)(xw + (size_t)s * 64))[c];
    float4* outp = (float4*)(agg + (size_t)d * 64) + c;
    red_add_v4(outp, v.x * norm, v.y * norm, v.z * norm, v.w * norm);
}

__global__ __launch_bounds__(256) void scatter2_kernel(
    const int2* __restrict__ e2, const float* __restrict__ deg,
    const float* __restrict__ xw, float* __restrict__ agg, int nedges) {
    long long t = (long long)blockIdx.x * blockDim.x + threadIdx.x;
    int e = (int)(t >> 4);
    int c = (int)(t & 15);
    if (e >= nedges) return;
    int2 sd = e2[e];
    if (sd.x < 0) return;
    float norm = rsqrtf(deg[sd.x] * deg[sd.y]);
    float4 v = ((const float4*)(xw + (size_t)sd.x * 64))[c];
    float4* outp = (float4*)(agg + (size_t)sd.y * 64) + c;
    red_add_v4(outp, v.x * norm, v.y * norm, v.z * norm, v.w * norm);
}

// ---------------- conv epilogue: h = relu(agg + xw/deg + b); score = tanh(h.p/||p||)
__global__ __launch_bounds__(256) void epilogue_kernel(
    const float* __restrict__ agg, const float* __restrict__ xw,
    const float* __restrict__ deg, const float* __restrict__ b,
    const float* __restrict__ p, float* __restrict__ h,
    float* __restrict__ score, int n) {
    int warp = (blockIdx.x * blockDim.x + threadIdx.x) >> 5;
    int lane = threadIdx.x & 31;
    if (warp >= n) return;
    float invd = 1.0f / deg[warp];
    size_t base = (size_t)warp * 64;
    float v0 = fmaxf(agg[base + lane]      + xw[base + lane]      * invd + b[lane], 0.f);
    float v1 = fmaxf(agg[base + lane + 32] + xw[base + lane + 32] * invd + b[lane + 32], 0.f);
    h[base + lane]      = v0;
    h[base + lane + 32] = v1;
    float pe0 = p[lane], pe1 = p[lane + 32];
    float dot = v0 * pe0 + v1 * pe1;
    float pp  = pe0 * pe0 + pe1 * pe1;
#pragma unroll
    for (int o = 16; o; o >>= 1) {
        dot += __shfl_down_sync(0xFFFFFFFFu, dot, o);
        pp  += __shfl_down_sync(0xFFFFFFFFu, pp, o);
    }
    if (lane == 0) score[warp] = tanhf(dot * rsqrtf(pp));
}

// ---------------- per-graph top-k via in-smem bitonic sort ------------------
// key (ascending) = (~ord(score) << 32) | index  => descending score, ascending index (jax tie-break)
__global__ __launch_bounds__(256) void topk_kernel(
    const float* __restrict__ score, int n_per, int k,
    int* __restrict__ perm, float* __restrict__ vals, int* __restrict__ newid) {
    __shared__ unsigned long long keys[2048];
    int b = blockIdx.x;
    int tid = threadIdx.x;
    const float* sc = score + (size_t)b * n_per;
    for (int i = tid; i < 2048; i += 256) {
        unsigned long long key;
        if (i < n_per) {
            unsigned u = __float_as_uint(sc[i]);
            u = (u & 0x80000000u) ? ~u : (u | 0x80000000u);
            key = ((unsigned long long)(~u) << 32) | (unsigned)i;
        } else {
            key = 0xFFFFFFFFFFFFFFFFull;
        }
        keys[i] = key;
    }
    __syncthreads();
    for (int kk = 2; kk <= 2048; kk <<= 1) {
        for (int jj = kk >> 1; jj > 0; jj >>= 1) {
            for (int i = tid; i < 2048; i += 256) {
                int ixj = i ^ jj;
                if (ixj > i) {
                    unsigned long long a = keys[i], c = keys[ixj];
                    bool swap = ((i & kk) == 0) ? (a > c) : (a < c);
                    if (swap) { keys[i] = c; keys[ixj] = a; }
                }
            }
            __syncthreads();
        }
    }
    for (int r = tid; r < k; r += 256) {
        int idx = (int)(keys[r] & 0xFFFFFFFFull);
        int g_old = b * n_per + idx;
        perm[b * k + r] = g_old;
        vals[b * k + r] = sc[idx];
        if (newid) newid[g_old] = b * k + r;
    }
}

// ---------------- gather + gate: xp[nid] = h[perm[nid]] * vals[nid] ----------
__global__ __launch_bounds__(256) void gather_gate_kernel(
    const float* __restrict__ h, const int* __restrict__ perm,
    const float* __restrict__ vals, float* __restrict__ xp, int nnodes) {
    long long t = (long long)blockIdx.x * blockDim.x + threadIdx.x;
    int nid = (int)(t >> 4);
    int c = (int)(t & 15);
    if (nid >= nnodes) return;
    float val = vals[nid];
    float4 v = ((const float4*)(h + (size_t)perm[nid] * 64))[c];
    ((float4*)(xp + (size_t)nid * 64))[c] =
        make_float4(v.x * val, v.y * val, v.z * val, v.w * val);
}

// ---------------- per-graph [max | mean] readout -----------------------------
__global__ __launch_bounds__(64) void maxmean_kernel(
    const float* __restrict__ x, int n_per, float* __restrict__ out) {
    int b = blockIdx.x;
    int j = threadIdx.x;     // 64 threads, column each
    float mx = -INFINITY, sum = 0.f;
    const float* p = x + (size_t)b * n_per * 64 + j;
    for (int r = 0; r < n_per; r++) {
        float v = p[(size_t)r * 64];
        mx = fmaxf(mx, v);
        sum += v;
    }
    out[b * 128 + j]      = mx;
    out[b * 128 + 64 + j] = sum / (float)n_per;
}

// ---------------- MLP head: out = relu((x1+x2)@lin1 + b)@lin2 + b ------------
__global__ __launch_bounds__(64) void head_kernel(
    const float* __restrict__ x1, const float* __restrict__ x2,
    const float* __restrict__ l1w, const float* __restrict__ l1b,
    const float* __restrict__ l2w, const float* __restrict__ l2b,
    float* __restrict__ out) {
    int b = blockIdx.x;
    int j = threadIdx.x;  // 64
    __shared__ float hv[128];
    __shared__ float h1[64];
    hv[j]      = x1[b * 128 + j]      + x2[b * 128 + j];
    hv[j + 64] = x1[b * 128 + 64 + j] + x2[b * 128 + 64 + j];
    __syncthreads();
    float acc = l1b[j];
#pragma unroll 8
    for (int k = 0; k < 128; k++) acc += hv[k] * l1w[k * 64 + j];
    h1[j] = fmaxf(acc, 0.f);
    __syncthreads();
    if (j < NCLS) {
        float o = l2b[j];
#pragma unroll 8
        for (int kk = 0; kk < 64; kk++) o += h1[kk] * l2w[kk * NCLS + j];
        out[b * NCLS + j] = o;
    }
}

// ---------------- host orchestration ----------------------------------------
extern "C" void kernel_launch(void* const* d_in, const int* in_sizes, int n_in,
                              void* d_out, int out_size) {
    const float* x   = (const float*)d_in[0];
    const int* ei    = (const int*)d_in[1];
    // d_in[2] = batch (unused; structure is regular)
    const float* W1  = (const float*)d_in[3];
    const float* b1  = (const float*)d_in[4];
    const float* p1  = (const float*)d_in[5];
    const float* W2  = (const float*)d_in[6];
    const float* b2  = (const float*)d_in[7];
    const float* p2  = (const float*)d_in[8];
    const float* l1w = (const float*)d_in[9];
    const float* l1b = (const float*)d_in[10];
    const float* l2w = (const float*)d_in[11];
    const float* l2b = (const float*)d_in[12];
    float* out = (float*)d_out;

    const int* src = ei;
    const int* dst = ei + EDG;

    float *xw, *agg, *h, *xp, *deg, *score, *vals, *x1, *x2;
    int *perm, *newid;
    int2* e2;
    cudaGetSymbolAddress((void**)&xw,    g_xw);
    cudaGetSymbolAddress((void**)&agg,   g_agg);
    cudaGetSymbolAddress((void**)&h,     g_h);
    cudaGetSymbolAddress((void**)&xp,    g_xp);
    cudaGetSymbolAddress((void**)&deg,   g_deg);
    cudaGetSymbolAddress((void**)&score, g_score);
    cudaGetSymbolAddress((void**)&vals,  g_vals);
    cudaGetSymbolAddress((void**)&x1,    g_x1);
    cudaGetSymbolAddress((void**)&x2,    g_x2);
    cudaGetSymbolAddress((void**)&perm,  g_perm);
    cudaGetSymbolAddress((void**)&newid, g_newid);
    cudaGetSymbolAddress((void**)&e2,    g_e2);

    const int TB = 256;

    // ===================== Stage 1 =====================
    fill_f_kernel<<<2048, TB>>>(deg, 1.0f, NTOT);
    deg1_kernel<<<(EDG + TB - 1) / TB, TB>>>(dst, deg, EDG);

    matmul64_kernel<<<NTOT / 32, TB>>>(x, W1, xw, NTOT);

    fill_f_kernel<<<4096, TB>>>(agg, 0.0f, (long long)NTOT * 64);
    scatter1_kernel<<<(int)(((long long)EDG * 16 + TB - 1) / TB), TB>>>(src, dst, deg, xw, agg, EDG);

    epilogue_kernel<<<(NTOT * 32 + TB - 1) / TB, TB>>>(agg, xw, deg, b1, p1, h, score, NTOT);

    fill_i_kernel<<<1024, TB>>>(newid, -1, NTOT);
    topk_kernel<<<BG, TB>>>(score, NPG, K1, perm, vals, newid);

    gather_gate_kernel<<<(int)(((long long)NT1 * 16 + TB - 1) / TB), TB>>>(h, perm, vals, xp, NT1);
    maxmean_kernel<<<BG, 64>>>(xp, K1, x1);

    // ===================== Stage 2 =====================
    fill_f_kernel<<<1024, TB>>>(deg, 1.0f, NT1);
    edge_map_kernel<<<(EDG + TB - 1) / TB, TB>>>(src, dst, newid, e2, deg, EDG);

    matmul64_kernel<<<(NT1 + 31) / 32, TB>>>(xp, W2, xw, NT1);

    fill_f_kernel<<<4096, TB>>>(agg, 0.0f, (long long)NT1 * 64);
    scatter2_kernel<<<(int)(((long long)EDG * 16 + TB - 1) / TB), TB>>>(e2, deg, xw, agg, EDG);

    epilogue_kernel<<<(NT1 * 32 + TB - 1) / TB, TB>>>(agg, xw, deg, b2, p2, h, score, NT1);

    topk_kernel<<<BG, TB>>>(score, K1, K2, perm, vals, (int*)nullptr);

    gather_gate_kernel<<<(int)(((long long)NT2 * 16 + TB - 1) / TB), TB>>>(h, perm, vals, xp, NT2);
    maxmean_kernel<<<BG, 64>>>(xp, K2, x2);

    // ===================== Head =====================
    head_kernel<<<BG, 64>>>(x1, x2, l1w, l1b, l2w, l2b, out);
}

// round 2
// speedup vs baseline: 1.2400x; 1.2400x over previous
#include <cuda_runtime.h>
#include <cuda_bf16.h>
#include <math.h>

#define BG   64
#define NPG  2048
#define EPG  32768
#define NTOT (BG * NPG)         // 131072
#define EDG  (BG * EPG)         // 2097152
#define K1   1639
#define NT1  (BG * K1)          // 104896
#define K2   1312
#define NT2  (BG * K2)          // 83968
#define DIM  64
#define NCLS 6
#define FULLMASK 0xFFFFFFFFu

// ---------------- scratch ----------------------------------------------------
__device__ float g_xw[NTOT * DIM];     // x@W (stage1), gathered-xp@W2 (stage2)
__device__ float g_h[NTOT * DIM];      // conv output (relu'd)
__device__ float g_score[NTOT];
__device__ float g_rdeg[NTOT];         // rsqrt(deg)
__device__ int   g_cnt[NTOT];          // in-degree (excl self-loop)
__device__ int   g_offs[NTOT];         // CSR offsets
__device__ int   g_cursor[NTOT];
__device__ int   g_elist[EDG];         // CSR: src per dst-slot
__device__ int   g_exscan[NTOT];       // scan scratch
__device__ int   g_bsums[256];
__device__ int   g_perm[NT1];
__device__ float g_vals[NT1];
__device__ int   g_newid[NTOT];
__device__ int2  g_e2[EDG];            // remapped (s2,d2) or (-1,-1)
__device__ float g_x1[BG * 2 * DIM];
__device__ float g_x2[BG * 2 * DIM];

// ---------------- utility ----------------------------------------------------
__global__ void fill_i_kernel(int* p, int v, int n) {
    int t = blockIdx.x * blockDim.x + threadIdx.x;
    int stride = gridDim.x * blockDim.x;
    for (; t < n; t += stride) p[t] = v;
}

// histogram of dst (stage 1: all edges valid)
__global__ void cnt1_kernel(const int* __restrict__ dst, int* __restrict__ cnt, int nedges) {
    int t = blockIdx.x * blockDim.x + threadIdx.x;
    if (t < nedges) atomicAdd(&cnt[dst[t]], 1);
}

// remap edges through newid; store pairs; histogram valid dst
__global__ void edge_map_kernel(const int* __restrict__ src, const int* __restrict__ dst,
                                const int* __restrict__ newid, int2* __restrict__ e2,
                                int* __restrict__ cnt, int nedges) {
    int t = blockIdx.x * blockDim.x + threadIdx.x;
    if (t >= nedges) return;
    int s2 = newid[src[t]];
    int d2 = newid[dst[t]];
    if (s2 < 0 || d2 < 0) {
        e2[t] = make_int2(-1, -1);
    } else {
        e2[t] = make_int2(s2, d2);
        atomicAdd(&cnt[d2], 1);
    }
}

// ---------------- 3-kernel exclusive scan ------------------------------------
__global__ __launch_bounds__(1024) void scan_block_kernel(
    const int* __restrict__ cnt, int* __restrict__ ex, int* __restrict__ bsums, int n) {
    __shared__ int s[1024];
    int tid = threadIdx.x;
    int i = blockIdx.x * 1024 + tid;
    int v = (i < n) ? cnt[i] : 0;
    s[tid] = v;
    __syncthreads();
    for (int off = 1; off < 1024; off <<= 1) {
        int t = (tid >= off) ? s[tid - off] : 0;
        __syncthreads();
        s[tid] += t;
        __syncthreads();
    }
    if (i < n) ex[i] = s[tid] - v;
    if (tid == 1023) bsums[blockIdx.x] = s[1023];
}
__global__ __launch_bounds__(256) void scan_top_kernel(int* bsums, int nb) {
    __shared__ int s[256];
    int tid = threadIdx.x;
    int v = (tid < nb) ? bsums[tid] : 0;
    s[tid] = v;
    __syncthreads();
    for (int off = 1; off < 256; off <<= 1) {
        int t = (tid >= off) ? s[tid - off] : 0;
        __syncthreads();
        s[tid] += t;
        __syncthreads();
    }
    if (tid < nb) bsums[tid] = s[tid] - v;
}
__global__ void scan_finish_kernel(const int* __restrict__ ex, const int* __restrict__ bsums,
                                   const int* __restrict__ cnt, int* __restrict__ offs,
                                   int* __restrict__ cursor, float* __restrict__ rdeg, int n) {
    int i = blockIdx.x * blockDim.x + threadIdx.x;
    if (i >= n) return;
    int o = ex[i] + bsums[i >> 10];
    offs[i] = o;
    cursor[i] = o;
    rdeg[i] = rsqrtf((float)(cnt[i] + 1));
}

// ---------------- CSR placement ----------------------------------------------
__global__ void place1_kernel(const int* __restrict__ src, const int* __restrict__ dst,
                              int* __restrict__ cursor, int* __restrict__ elist, int nedges) {
    int t = blockIdx.x * blockDim.x + threadIdx.x;
    if (t >= nedges) return;
    int slot = atomicAdd(&cursor[dst[t]], 1);
    elist[slot] = src[t];
}
__global__ void place2_kernel(const int2* __restrict__ e2, int* __restrict__ cursor,
                              int* __restrict__ elist, int nedges) {
    int t = blockIdx.x * blockDim.x + threadIdx.x;
    if (t >= nedges) return;
    int2 sd = e2[t];
    if (sd.x < 0) return;
    int slot = atomicAdd(&cursor[sd.y], 1);
    elist[slot] = sd.x;
}

// ---------------- GEMM: C[n x 64] = gather(A)[n x 64] @ W[64 x 64] ----------
// If perm != nullptr, row i of A is A[perm[i]] * vals[i] (fused TopK gather+gate).
__global__ __launch_bounds__(256) void matmul64_kernel(
    const float* __restrict__ A, const float* __restrict__ W,
    const int* __restrict__ perm, const float* __restrict__ vals,
    float* __restrict__ C, int nrows) {
    __shared__ float Wt[64][68];
    __shared__ float As[32][64];
    int tid = threadIdx.x;
    for (int i = tid; i < 64 * 64; i += 256) {
        int k = i >> 6, j = i & 63;
        Wt[j][k] = W[i];
    }
    int row0 = blockIdx.x * 32;
    {
        float4* s4 = (float4*)&As[0][0];
        for (int i = tid; i < 512; i += 256) {
            int grow = row0 + (i >> 4);
            float4 v = make_float4(0.f, 0.f, 0.f, 0.f);
            if (grow < nrows) {
                int arow = perm ? perm[grow] : grow;
                float sc = perm ? vals[grow] : 1.0f;
                v = ((const float4*)(A + (size_t)arow * 64))[i & 15];
                v.x *= sc; v.y *= sc; v.z *= sc; v.w *= sc;
            }
            s4[i] = v;
        }
    }
    __syncthreads();
    int j  = tid & 31;
    int rg = tid >> 5;
    float acc[4][2] = {};
#pragma unroll
    for (int k4 = 0; k4 < 16; k4++) {
        float4 w0 = *(const float4*)&Wt[j][k4 * 4];
        float4 w1 = *(const float4*)&Wt[j + 32][k4 * 4];
#pragma unroll
        for (int r = 0; r < 4; r++) {
            float4 a = *(const float4*)&As[rg * 4 + r][k4 * 4];
            acc[r][0] += a.x * w0.x + a.y * w0.y + a.z * w0.z + a.w * w0.w;
            acc[r][1] += a.x * w1.x + a.y * w1.y + a.z * w1.z + a.w * w1.w;
        }
    }
#pragma unroll
    for (int r = 0; r < 4; r++) {
        int row = row0 + rg * 4 + r;
        if (row < nrows) {
            C[(size_t)row * 64 + j]      = acc[r][0];
            C[(size_t)row * 64 + j + 32] = acc[r][1];
        }
    }
}

// ---------------- fused CSR-gather conv + epilogue + score -------------------
// One warp per dst node: acc = sum_e rdeg[s]*rdeg[d]*xw[s] + rdeg[d]^2*xw[d] + b
// h = relu(acc); score = tanh(h.p / ||p||)
__global__ __launch_bounds__(256) void conv_kernel(
    const int* __restrict__ offs, const int* __restrict__ cnt,
    const int* __restrict__ elist, const float* __restrict__ rdeg,
    const float* __restrict__ xw, const float* __restrict__ bias,
    const float* __restrict__ p, float* __restrict__ h,
    float* __restrict__ score, int n) {
    int warp = (blockIdx.x * blockDim.x + threadIdx.x) >> 5;
    int lane = threadIdx.x & 31;
    if (warp >= n) return;
    const float2* xw2 = (const float2*)xw;
    float rd = rdeg[warp];
    int start = offs[warp];
    int m = cnt[warp];
    float2 acc = make_float2(0.f, 0.f);
    for (int base = 0; base < m; base += 32) {
        int s = 0; float r = 0.f;
        if (base + lane < m) {
            s = elist[start + base + lane];
            r = rdeg[s];
        }
        int lim = min(32, m - base);
        for (int k = 0; k < lim; k++) {
            int ss = __shfl_sync(FULLMASK, s, k);
            float nr = __shfl_sync(FULLMASK, r, k) * rd;
            float2 v = xw2[(size_t)ss * 32 + lane];
            acc.x += nr * v.x;
            acc.y += nr * v.y;
        }
    }
    // self-loop: coefficient 1/deg = rdeg^2
    float2 vs = xw2[(size_t)warp * 32 + lane];
    float2 bb = ((const float2*)bias)[lane];
    float inv = rd * rd;
    acc.x = fmaxf(acc.x + vs.x * inv + bb.x, 0.f);
    acc.y = fmaxf(acc.y + vs.y * inv + bb.y, 0.f);
    ((float2*)h)[(size_t)warp * 32 + lane] = acc;
    float2 pe = ((const float2*)p)[lane];
    float dot = acc.x * pe.x + acc.y * pe.y;
    float pp  = pe.x * pe.x + pe.y * pe.y;
#pragma unroll
    for (int o = 16; o; o >>= 1) {
        dot += __shfl_down_sync(FULLMASK, dot, o);
        pp  += __shfl_down_sync(FULLMASK, pp, o);
    }
    if (lane == 0) score[warp] = tanhf(dot * rsqrtf(pp));
}

// ---------------- per-graph top-k via bitonic sort ---------------------------
__global__ __launch_bounds__(512) void topk_kernel(
    const float* __restrict__ score, int n_per, int k,
    int* __restrict__ perm, float* __restrict__ vals, int* __restrict__ newid) {
    __shared__ unsigned long long keys[2048];
    int b = blockIdx.x;
    int tid = threadIdx.x;
    const float* sc = score + (size_t)b * n_per;
    for (int i = tid; i < 2048; i += 512) {
        unsigned long long key;
        if (i < n_per) {
            unsigned u = __float_as_uint(sc[i]);
            u = (u & 0x80000000u) ? ~u : (u | 0x80000000u);
            key = ((unsigned long long)(~u) << 32) | (unsigned)i;
        } else {
            key = 0xFFFFFFFFFFFFFFFFull;
        }
        keys[i] = key;
    }
    __syncthreads();
    for (int kk = 2; kk <= 2048; kk <<= 1) {
        for (int jj = kk >> 1; jj > 0; jj >>= 1) {
            for (int i = tid; i < 2048; i += 512) {
                int ixj = i ^ jj;
                if (ixj > i) {
                    unsigned long long a = keys[i], c = keys[ixj];
                    bool swap = ((i & kk) == 0) ? (a > c) : (a < c);
                    if (swap) { keys[i] = c; keys[ixj] = a; }
                }
            }
            __syncthreads();
        }
    }
    for (int r = tid; r < k; r += 512) {
        int idx = (int)(keys[r] & 0xFFFFFFFFull);
        int g_old = b * n_per + idx;
        perm[b * k + r] = g_old;
        vals[b * k + r] = sc[idx];
        if (newid) newid[g_old] = b * k + r;
    }
}

// ---------------- per-graph [max | mean] over gathered+gated rows ------------
__global__ __launch_bounds__(512) void maxmean_kernel(
    const float* __restrict__ h, const int* __restrict__ perm,
    const float* __restrict__ vals, int k, float* __restrict__ out) {
    __shared__ float smx[512], ssm[512];
    int b = blockIdx.x;
    int tid = threadIdx.x;
    int j = tid & 63;
    int rg = tid >> 6;          // 0..7
    float mx = -INFINITY, sum = 0.f;
    for (int r = rg; r < k; r += 8) {
        int idx = perm[b * k + r];
        float v = h[(size_t)idx * 64 + j] * vals[b * k + r];
        mx = fmaxf(mx, v);
        sum += v;
    }
    smx[tid] = mx;
    ssm[tid] = sum;
    __syncthreads();
    for (int s = 4; s >= 1; s >>= 1) {
        if (rg < s) {
            smx[rg * 64 + j] = fmaxf(smx[rg * 64 + j], smx[(rg + s) * 64 + j]);
            ssm[rg * 64 + j] += ssm[(rg + s) * 64 + j];
        }
        __syncthreads();
    }
    if (rg == 0) {
        out[b * 128 + j]      = smx[j];
        out[b * 128 + 64 + j] = ssm[j] / (float)k;
    }
}

// ---------------- MLP head ---------------------------------------------------
__global__ __launch_bounds__(64) void head_kernel(
    const float* __restrict__ x1, const float* __restrict__ x2,
    const float* __restrict__ l1w, const float* __restrict__ l1b,
    const float* __restrict__ l2w, const float* __restrict__ l2b,
    float* __restrict__ out) {
    int b = blockIdx.x;
    int j = threadIdx.x;
    __shared__ float hv[128];
    __shared__ float h1[64];
    hv[j]      = x1[b * 128 + j]      + x2[b * 128 + j];
    hv[j + 64] = x1[b * 128 + 64 + j] + x2[b * 128 + 64 + j];
    __syncthreads();
    float acc = l1b[j];
#pragma unroll 8
    for (int k = 0; k < 128; k++) acc += hv[k] * l1w[k * 64 + j];
    h1[j] = fmaxf(acc, 0.f);
    __syncthreads();
    if (j < NCLS) {
        float o = l2b[j];
#pragma unroll 8
        for (int kk = 0; kk < 64; kk++) o += h1[kk] * l2w[kk * NCLS + j];
        out[b * NCLS + j] = o;
    }
}

// ---------------- host orchestration ----------------------------------------
extern "C" void kernel_launch(void* const* d_in, const int* in_sizes, int n_in,
                              void* d_out, int out_size) {
    const float* x   = (const float*)d_in[0];
    const int* ei    = (const int*)d_in[1];
    const float* W1  = (const float*)d_in[3];
    const float* b1  = (const float*)d_in[4];
    const float* p1  = (const float*)d_in[5];
    const float* W2  = (const float*)d_in[6];
    const float* b2  = (const float*)d_in[7];
    const float* p2  = (const float*)d_in[8];
    const float* l1w = (const float*)d_in[9];
    const float* l1b = (const float*)d_in[10];
    const float* l2w = (const float*)d_in[11];
    const float* l2b = (const float*)d_in[12];
    float* out = (float*)d_out;

    const int* src = ei;
    const int* dst = ei + EDG;

    float *xw, *h, *score, *rdeg, *vals, *x1, *x2;
    int *cnt, *offs, *cursor, *elist, *exs, *bsums, *perm, *newid;
    int2* e2;
    cudaGetSymbolAddress((void**)&xw,     g_xw);
    cudaGetSymbolAddress((void**)&h,      g_h);
    cudaGetSymbolAddress((void**)&score,  g_score);
    cudaGetSymbolAddress((void**)&rdeg,   g_rdeg);
    cudaGetSymbolAddress((void**)&cnt,    g_cnt);
    cudaGetSymbolAddress((void**)&offs,   g_offs);
    cudaGetSymbolAddress((void**)&cursor, g_cursor);
    cudaGetSymbolAddress((void**)&elist,  g_elist);
    cudaGetSymbolAddress((void**)&exs,    g_exscan);
    cudaGetSymbolAddress((void**)&bsums,  g_bsums);
    cudaGetSymbolAddress((void**)&perm,   g_perm);
    cudaGetSymbolAddress((void**)&newid,  g_newid);
    cudaGetSymbolAddress((void**)&e2,     g_e2);
    cudaGetSymbolAddress((void**)&vals,   g_vals);
    cudaGetSymbolAddress((void**)&x1,     g_x1);
    cudaGetSymbolAddress((void**)&x2,     g_x2);

    const int TB = 256;
    const int EB = (EDG + TB - 1) / TB;

    // ===================== Stage 1 =====================
    fill_i_kernel<<<512, TB>>>(cnt, 0, NTOT);
    cnt1_kernel<<<EB, TB>>>(dst, cnt, EDG);
    {
        int nb = (NTOT + 1023) / 1024;
        scan_block_kernel<<<nb, 1024>>>(cnt, exs, bsums, NTOT);
        scan_top_kernel<<<1, 256>>>(bsums, nb);
        scan_finish_kernel<<<(NTOT + TB - 1) / TB, TB>>>(exs, bsums, cnt, offs, cursor, rdeg, NTOT);
    }
    place1_kernel<<<EB, TB>>>(src, dst, cursor, elist, EDG);

    matmul64_kernel<<<NTOT / 32, TB>>>(x, W1, nullptr, nullptr, xw, NTOT);
    conv_kernel<<<(NTOT * 32 + TB - 1) / TB, TB>>>(offs, cnt, elist, rdeg, xw, b1, p1, h, score, NTOT);

    fill_i_kernel<<<512, TB>>>(newid, -1, NTOT);
    topk_kernel<<<BG, 512>>>(score, NPG, K1, perm, vals, newid);
    maxmean_kernel<<<BG, 512>>>(h, perm, vals, K1, x1);

    // ===================== Stage 2 =====================
    fill_i_kernel<<<512, TB>>>(cnt, 0, NT1);
    edge_map_kernel<<<EB, TB>>>(src, dst, newid, e2, cnt, EDG);
    {
        int nb = (NT1 + 1023) / 1024;
        scan_block_kernel<<<nb, 1024>>>(cnt, exs, bsums, NT1);
        scan_top_kernel<<<1, 256>>>(bsums, nb);
        scan_finish_kernel<<<(NT1 + TB - 1) / TB, TB>>>(exs, bsums, cnt, offs, cursor, rdeg, NT1);
    }
    place2_kernel<<<EB, TB>>>(e2, cursor, elist, EDG);

    matmul64_kernel<<<(NT1 + 31) / 32, TB>>>(h, W2, perm, vals, xw, NT1);
    conv_kernel<<<(NT1 * 32 + TB - 1) / TB, TB>>>(offs, cnt, elist, rdeg, xw, b2, p2, h, score, NT1);

    topk_kernel<<<BG, 512>>>(score, K1, K2, perm, vals, (int*)nullptr);
    maxmean_kernel<<<BG, 512>>>(h, perm, vals, K2, x2);

    // ===================== Head =====================
    head_kernel<<<BG, 64>>>(x1, x2, l1w, l1b, l2w, l2b, out);
}

// round 3
// speedup vs baseline: 1.6481x; 1.3291x over previous
#include <cuda_runtime.h>
#include <cuda_bf16.h>
#include <math.h>

#define BG   64
#define NPG  2048
#define EPG  32768
#define NTOT (BG * NPG)         // 131072
#define EDG  (BG * EPG)         // 2097152
#define K1   1639
#define NT1  (BG * K1)          // 104896
#define K2   1312
#define NT2  (BG * K2)          // 83968
#define DIM  64
#define NCLS 6
#define CAP  64                 // fixed CSR bucket capacity (P(deg>=64) ~ 1e-20)
#define FULLMASK 0xFFFFFFFFu

// ---------------- scratch ----------------------------------------------------
__device__ float g_xw[NTOT * DIM];       // x@W (stage1), gathered-xp@W2 (stage2)
__device__ float g_h[NTOT * DIM];        // conv output (relu'd)
__device__ float g_score[NTOT];
__device__ float g_rdeg[NTOT];           // rsqrt(deg incl self-loop)
__device__ int   g_cnt[NTOT];            // in-degree (excl self-loop)
__device__ int   g_elist[NTOT * CAP];    // fixed-stride CSR: src per dst-slot
__device__ int   g_perm[NT1];
__device__ float g_vals[NT1];
__device__ int   g_newid[NTOT];
__device__ float g_x1[BG * 2 * DIM];
__device__ float g_x2[BG * 2 * DIM];

// ---------------- utility ----------------------------------------------------
__global__ void fill_i_kernel(int* p, int v, int n) {
    int t = blockIdx.x * blockDim.x + threadIdx.x;
    int stride = gridDim.x * blockDim.x;
    for (; t < n; t += stride) p[t] = v;
}

// fused count + place (stage 1: all edges valid)
__global__ void place1_kernel(const int* __restrict__ src, const int* __restrict__ dst,
                              int* __restrict__ cnt, int* __restrict__ elist, int nedges) {
    int t = blockIdx.x * blockDim.x + threadIdx.x;
    if (t >= nedges) return;
    int d = dst[t];
    int slot = atomicAdd(&cnt[d], 1);
    elist[d * CAP + slot] = src[t];
}

// fused remap + count + place (stage 2)
__global__ void place2_kernel(const int* __restrict__ src, const int* __restrict__ dst,
                              const int* __restrict__ newid,
                              int* __restrict__ cnt, int* __restrict__ elist, int nedges) {
    int t = blockIdx.x * blockDim.x + threadIdx.x;
    if (t >= nedges) return;
    int s2 = newid[src[t]];
    int d2 = newid[dst[t]];
    if (s2 < 0 || d2 < 0) return;
    int slot = atomicAdd(&cnt[d2], 1);
    elist[d2 * CAP + slot] = s2;
}

__global__ void rdeg_kernel(const int* __restrict__ cnt, float* __restrict__ rdeg, int n) {
    int i = blockIdx.x * blockDim.x + threadIdx.x;
    if (i < n) rdeg[i] = rsqrtf((float)(cnt[i] + 1));
}

// ---------------- GEMM: C[n x 64] = gather(A)[n x 64] @ W[64 x 64] ----------
// If perm != nullptr, row i of A is A[perm[i]] * vals[i] (fused TopK gather+gate).
__global__ __launch_bounds__(256) void matmul64_kernel(
    const float* __restrict__ A, const float* __restrict__ W,
    const int* __restrict__ perm, const float* __restrict__ vals,
    float* __restrict__ C, int nrows) {
    __shared__ float Wt[64][68];
    __shared__ float As[32][64];
    int tid = threadIdx.x;
    for (int i = tid; i < 64 * 64; i += 256) {
        int k = i >> 6, j = i & 63;
        Wt[j][k] = W[i];
    }
    int row0 = blockIdx.x * 32;
    {
        float4* s4 = (float4*)&As[0][0];
        for (int i = tid; i < 512; i += 256) {
            int grow = row0 + (i >> 4);
            float4 v = make_float4(0.f, 0.f, 0.f, 0.f);
            if (grow < nrows) {
                int arow = perm ? perm[grow] : grow;
                float sc = perm ? vals[grow] : 1.0f;
                v = ((const float4*)(A + (size_t)arow * 64))[i & 15];
                v.x *= sc; v.y *= sc; v.z *= sc; v.w *= sc;
            }
            s4[i] = v;
        }
    }
    __syncthreads();
    int j  = tid & 31;
    int rg = tid >> 5;
    float acc[4][2] = {};
#pragma unroll
    for (int k4 = 0; k4 < 16; k4++) {
        float4 w0 = *(const float4*)&Wt[j][k4 * 4];
        float4 w1 = *(const float4*)&Wt[j + 32][k4 * 4];
#pragma unroll
        for (int r = 0; r < 4; r++) {
            float4 a = *(const float4*)&As[rg * 4 + r][k4 * 4];
            acc[r][0] += a.x * w0.x + a.y * w0.y + a.z * w0.z + a.w * w0.w;
            acc[r][1] += a.x * w1.x + a.y * w1.y + a.z * w1.z + a.w * w1.w;
        }
    }
#pragma unroll
    for (int r = 0; r < 4; r++) {
        int row = row0 + rg * 4 + r;
        if (row < nrows) {
            C[(size_t)row * 64 + j]      = acc[r][0];
            C[(size_t)row * 64 + j + 32] = acc[r][1];
        }
    }
}

// ---------------- fused CSR-gather conv + epilogue + score -------------------
// One warp per dst node; the two half-warps each process alternate edges with
// float4 lanes (16 lanes x 16B = full 64-float row), combined at the end.
__global__ __launch_bounds__(256) void conv_kernel(
    const int* __restrict__ cnt, const int* __restrict__ elist,
    const float* __restrict__ rdeg, const float* __restrict__ xw,
    const float* __restrict__ bias, const float* __restrict__ p,
    float* __restrict__ h, float* __restrict__ score, int n) {
    int warp = (blockIdx.x * blockDim.x + threadIdx.x) >> 5;
    int lane = threadIdx.x & 31;
    if (warp >= n) return;
    int li   = lane & 15;
    int half = lane >> 4;
    const float4* xw4 = (const float4*)xw;
    float rd = rdeg[warp];
    int m = cnt[warp];
    const int* el = elist + (size_t)warp * CAP;
    float4 acc = make_float4(0.f, 0.f, 0.f, 0.f);
#pragma unroll 2
    for (int e = half; e < m; e += 2) {
        int s = el[e];
        float nr = rdeg[s] * rd;
        float4 v = xw4[(size_t)s * 16 + li];
        acc.x += nr * v.x; acc.y += nr * v.y;
        acc.z += nr * v.z; acc.w += nr * v.w;
    }
    // combine halves (both halves end up with full sums)
    acc.x += __shfl_xor_sync(FULLMASK, acc.x, 16);
    acc.y += __shfl_xor_sync(FULLMASK, acc.y, 16);
    acc.z += __shfl_xor_sync(FULLMASK, acc.z, 16);
    acc.w += __shfl_xor_sync(FULLMASK, acc.w, 16);
    // self-loop (coef 1/deg = rd^2) + bias + relu
    float4 vs = xw4[(size_t)warp * 16 + li];
    float4 b4 = ((const float4*)bias)[li];
    float inv = rd * rd;
    acc.x = fmaxf(acc.x + vs.x * inv + b4.x, 0.f);
    acc.y = fmaxf(acc.y + vs.y * inv + b4.y, 0.f);
    acc.z = fmaxf(acc.z + vs.z * inv + b4.z, 0.f);
    acc.w = fmaxf(acc.w + vs.w * inv + b4.w, 0.f);
    if (half == 0) ((float4*)h)[(size_t)warp * 16 + li] = acc;
    // pooling score: tanh(h.p / ||p||). Both halves duplicate -> full-warp sums
    // are 2x; the sqrt(2) factor corrects dot/sqrt(pp).
    float4 p4 = ((const float4*)p)[li];
    float dot = acc.x * p4.x + acc.y * p4.y + acc.z * p4.z + acc.w * p4.w;
    float pp  = p4.x * p4.x + p4.y * p4.y + p4.z * p4.z + p4.w * p4.w;
#pragma unroll
    for (int o = 16; o; o >>= 1) {
        dot += __shfl_down_sync(FULLMASK, dot, o);
        pp  += __shfl_down_sync(FULLMASK, pp, o);
    }
    if (lane == 0) score[warp] = tanhf(dot * rsqrtf(pp) * 0.7071067811865476f);
}

// ---------------- per-graph top-k via bitonic sort (1024 threads) ------------
__global__ __launch_bounds__(1024) void topk_kernel(
    const float* __restrict__ score, int n_per, int k,
    int* __restrict__ perm, float* __restrict__ vals, int* __restrict__ newid) {
    __shared__ unsigned long long keys[2048];
    int b = blockIdx.x;
    int tid = threadIdx.x;
    const float* sc = score + (size_t)b * n_per;
#pragma unroll
    for (int i = tid; i < 2048; i += 1024) {
        unsigned long long key;
        if (i < n_per) {
            unsigned u = __float_as_uint(sc[i]);
            u = (u & 0x80000000u) ? ~u : (u | 0x80000000u);
            key = ((unsigned long long)(~u) << 32) | (unsigned)i;
        } else {
            key = 0xFFFFFFFFFFFFFFFFull;
        }
        keys[i] = key;
    }
    __syncthreads();
    for (int kk = 2; kk <= 2048; kk <<= 1) {
        for (int jj = kk >> 1; jj > 0; jj >>= 1) {
#pragma unroll
            for (int i = tid; i < 2048; i += 1024) {
                int ixj = i ^ jj;
                if (ixj > i) {
                    unsigned long long a = keys[i], c = keys[ixj];
                    bool swap = ((i & kk) == 0) ? (a > c) : (a < c);
                    if (swap) { keys[i] = c; keys[ixj] = a; }
                }
            }
            __syncthreads();
        }
    }
    for (int r = tid; r < k; r += 1024) {
        int idx = (int)(keys[r] & 0xFFFFFFFFull);
        int g_old = b * n_per + idx;
        perm[b * k + r] = g_old;
        vals[b * k + r] = sc[idx];
        if (newid) newid[g_old] = b * k + r;
    }
}

// ---------------- per-graph [max | mean] over gathered+gated rows ------------
__global__ __launch_bounds__(1024) void maxmean_kernel(
    const float* __restrict__ h, const int* __restrict__ perm,
    const float* __restrict__ vals, int k, float* __restrict__ out) {
    __shared__ float smx[1024], ssm[1024];
    int b = blockIdx.x;
    int tid = threadIdx.x;
    int j = tid & 63;
    int rg = tid >> 6;          // 0..15
    float mx = -INFINITY, sum = 0.f;
    for (int r = rg; r < k; r += 16) {
        int idx = perm[b * k + r];
        float v = h[(size_t)idx * 64 + j] * vals[b * k + r];
        mx = fmaxf(mx, v);
        sum += v;
    }
    smx[tid] = mx;
    ssm[tid] = sum;
    __syncthreads();
    for (int s = 8; s >= 1; s >>= 1) {
        if (rg < s) {
            smx[rg * 64 + j] = fmaxf(smx[rg * 64 + j], smx[(rg + s) * 64 + j]);
            ssm[rg * 64 + j] += ssm[(rg + s) * 64 + j];
        }
        __syncthreads();
    }
    if (rg == 0) {
        out[b * 128 + j]      = smx[j];
        out[b * 128 + 64 + j] = ssm[j] / (float)k;
    }
}

// ---------------- MLP head ---------------------------------------------------
__global__ __launch_bounds__(64) void head_kernel(
    const float* __restrict__ x1, const float* __restrict__ x2,
    const float* __restrict__ l1w, const float* __restrict__ l1b,
    const float* __restrict__ l2w, const float* __restrict__ l2b,
    float* __restrict__ out) {
    int b = blockIdx.x;
    int j = threadIdx.x;
    __shared__ float hv[128];
    __shared__ float h1[64];
    hv[j]      = x1[b * 128 + j]      + x2[b * 128 + j];
    hv[j + 64] = x1[b * 128 + 64 + j] + x2[b * 128 + 64 + j];
    __syncthreads();
    float acc = l1b[j];
#pragma unroll 8
    for (int k = 0; k < 128; k++) acc += hv[k] * l1w[k * 64 + j];
    h1[j] = fmaxf(acc, 0.f);
    __syncthreads();
    if (j < NCLS) {
        float o = l2b[j];
#pragma unroll 8
        for (int kk = 0; kk < 64; kk++) o += h1[kk] * l2w[kk * NCLS + j];
        out[b * NCLS + j] = o;
    }
}

// ---------------- host orchestration ----------------------------------------
extern "C" void kernel_launch(void* const* d_in, const int* in_sizes, int n_in,
                              void* d_out, int out_size) {
    const float* x   = (const float*)d_in[0];
    const int* ei    = (const int*)d_in[1];
    const float* W1  = (const float*)d_in[3];
    const float* b1  = (const float*)d_in[4];
    const float* p1  = (const float*)d_in[5];
    const float* W2  = (const float*)d_in[6];
    const float* b2  = (const float*)d_in[7];
    const float* p2  = (const float*)d_in[8];
    const float* l1w = (const float*)d_in[9];
    const float* l1b = (const float*)d_in[10];
    const float* l2w = (const float*)d_in[11];
    const float* l2b = (const float*)d_in[12];
    float* out = (float*)d_out;

    const int* src = ei;
    const int* dst = ei + EDG;

    float *xw, *h, *score, *rdeg, *vals, *x1, *x2;
    int *cnt, *elist, *perm, *newid;
    cudaGetSymbolAddress((void**)&xw,     g_xw);
    cudaGetSymbolAddress((void**)&h,      g_h);
    cudaGetSymbolAddress((void**)&score,  g_score);
    cudaGetSymbolAddress((void**)&rdeg,   g_rdeg);
    cudaGetSymbolAddress((void**)&cnt,    g_cnt);
    cudaGetSymbolAddress((void**)&elist,  g_elist);
    cudaGetSymbolAddress((void**)&perm,   g_perm);
    cudaGetSymbolAddress((void**)&newid,  g_newid);
    cudaGetSymbolAddress((void**)&vals,   g_vals);
    cudaGetSymbolAddress((void**)&x1,     g_x1);
    cudaGetSymbolAddress((void**)&x2,     g_x2);

    const int TB = 256;
    const int EB = (EDG + TB - 1) / TB;

    // ===================== Stage 1 =====================
    fill_i_kernel<<<256, TB>>>(cnt, 0, NTOT);
    place1_kernel<<<EB, TB>>>(src, dst, cnt, elist, EDG);
    rdeg_kernel<<<(NTOT + TB - 1) / TB, TB>>>(cnt, rdeg, NTOT);

    matmul64_kernel<<<NTOT / 32, TB>>>(x, W1, nullptr, nullptr, xw, NTOT);
    conv_kernel<<<(NTOT * 32 + TB - 1) / TB, TB>>>(cnt, elist, rdeg, xw, b1, p1, h, score, NTOT);

    fill_i_kernel<<<256, TB>>>(newid, -1, NTOT);
    topk_kernel<<<BG, 1024>>>(score, NPG, K1, perm, vals, newid);
    maxmean_kernel<<<BG, 1024>>>(h, perm, vals, K1, x1);

    // ===================== Stage 2 =====================
    fill_i_kernel<<<256, TB>>>(cnt, 0, NT1);
    place2_kernel<<<EB, TB>>>(src, dst, newid, cnt, elist, EDG);
    rdeg_kernel<<<(NT1 + TB - 1) / TB, TB>>>(cnt, rdeg, NT1);

    matmul64_kernel<<<(NT1 + 31) / 32, TB>>>(h, W2, perm, vals, xw, NT1);
    conv_kernel<<<(NT1 * 32 + TB - 1) / TB, TB>>>(cnt, elist, rdeg, xw, b2, p2, h, score, NT1);

    topk_kernel<<<BG, 1024>>>(score, K1, K2, perm, vals, (int*)nullptr);
    maxmean_kernel<<<BG, 1024>>>(h, perm, vals, K2, x2);

    // ===================== Head =====================
    head_kernel<<<BG, 64>>>(x1, x2, l1w, l1b, l2w, l2b, out);
}